// round 1
// baseline (speedup 1.0000x reference)
#include <cuda_runtime.h>

// Problem constants
#define NN 512      // tokens
#define DN 256      // d_node
#define DE 128      // d_edge
#define DH 32       // d_head
#define LN_EPS 1e-5f

// Scratch (device globals: no allocation allowed)
__device__ float g_left[NN * DH];
__device__ float g_right[NN * DH];
__device__ float g_T[NN * DH * DE];   // [n][j][e] = [512][32][128]

// ---------------- packed f32x2 helpers (sm_103a) ----------------
__device__ __forceinline__ unsigned long long pk2(float lo, float hi) {
    unsigned long long r;
    asm("mov.b64 %0, {%1, %2};" : "=l"(r) : "f"(lo), "f"(hi));
    return r;
}
__device__ __forceinline__ void fma2(unsigned long long& d,
                                     unsigned long long a,
                                     unsigned long long b) {
    asm("fma.rn.f32x2 %0, %1, %2, %0;" : "+l"(d) : "l"(a), "l"(b));
}
__device__ __forceinline__ void upk2(unsigned long long v, float& lo, float& hi) {
    asm("mov.b64 {%0, %1}, %2;" : "=f"(lo), "=f"(hi) : "l"(v));
}

// ---------------- P1: LayerNorm + left/right projections ----------------
// One block per token n. 256 threads.
__global__ void p1_kernel(const float* __restrict__ node,
                          const float* __restrict__ ln_w,
                          const float* __restrict__ ln_b,
                          const float* __restrict__ wl,
                          const float* __restrict__ bl,
                          const float* __restrict__ wr,
                          const float* __restrict__ br) {
    __shared__ float xs[DN];
    __shared__ float red1[8], red2[8];
    __shared__ float ps[4][64];

    int n = blockIdx.x;
    int tid = threadIdx.x;

    float v = node[n * DN + tid];

    // mean
    float s = v;
    #pragma unroll
    for (int o = 16; o; o >>= 1) s += __shfl_xor_sync(0xffffffffu, s, o);
    if ((tid & 31) == 0) red1[tid >> 5] = s;
    __syncthreads();
    float mu = 0.f;
    #pragma unroll
    for (int i = 0; i < 8; i++) mu += red1[i];
    mu *= (1.f / 256.f);

    // variance
    float d = v - mu;
    float q = d * d;
    #pragma unroll
    for (int o = 16; o; o >>= 1) q += __shfl_xor_sync(0xffffffffu, q, o);
    if ((tid & 31) == 0) red2[tid >> 5] = q;
    __syncthreads();
    float var = 0.f;
    #pragma unroll
    for (int i = 0; i < 8; i++) var += red2[i];
    var *= (1.f / 256.f);

    float rstd = rsqrtf(var + LN_EPS);
    xs[tid] = d * rstd * ln_w[tid] + ln_b[tid];
    __syncthreads();

    // projections: thread t -> (h = t&31, sel = left/right, part = quarter of k)
    int h = tid & 31;
    int sel = (tid >> 5) & 1;
    int part = tid >> 6;
    const float* __restrict__ w = sel ? wr : wl;
    int k0 = part * 64;
    float acc = 0.f;
    #pragma unroll 8
    for (int k = 0; k < 64; k++) acc += xs[k0 + k] * w[(k0 + k) * DH + h];
    ps[part][sel * 32 + h] = acc;
    __syncthreads();

    if (tid < 64) {
        float r = ps[0][tid] + ps[1][tid] + ps[2][tid] + ps[3][tid];
        if (tid < 32) g_left[n * DH + tid] = r + bl[tid];
        else          g_right[n * DH + (tid - 32)] = r + br[tid - 32];
    }
}

// ---------------- P2: T = left @ B, B = w_out viewed as [32][4096] ----------------
// grid (32 col-tiles x 16 n-tiles), 256 threads. Block computes T[32 n][128 col].
__global__ void p2_kernel(const float* __restrict__ w_out) {
    __shared__ float As[32 * 32];   // left slab [32 n][32 i]

    int nb = blockIdx.y * 32;
    int cb = blockIdx.x * 128;
    int tid = threadIdx.x;

    // fill As (coalesced float4)
    {
        int row = tid >> 3, qq = tid & 7;
        *(float4*)&As[row * 32 + qq * 4] =
            *(const float4*)(g_left + (nb + row) * DH + qq * 4);
    }
    __syncthreads();

    int col = cb + (tid & 127);
    int nset = tid >> 7;            // 0 or 1 -> n rows [nset*16, nset*16+16)
    float acc[16];
    #pragma unroll
    for (int r = 0; r < 16; r++) acc[r] = 0.f;

    #pragma unroll 4
    for (int i = 0; i < 32; i++) {
        float b = w_out[i * 4096 + col];   // w_out[i*32+j][e] == flat[i*4096 + col]
        #pragma unroll
        for (int r = 0; r < 16; r++)
            acc[r] += As[(nset * 16 + r) * 32 + i] * b;
    }

    #pragma unroll
    for (int r = 0; r < 16; r++)
        g_T[(nb + nset * 16 + r) * (DH * DE) + col] = acc[r];
}

// ---------------- Main kernel: out = edge + b_out + right @ T ----------------
// grid (4 m-tiles, 512 n), 256 threads, 2 blocks/SM.
// Per thread: 16 m x 4 e register tile as 32 packed f32x2 accumulators (m-pairs).
__global__ void __launch_bounds__(256, 2)
outk_kernel(const float* __restrict__ edge,
            const float* __restrict__ b_out,
            float* __restrict__ out) {
    __shared__ __align__(16) float sT[DH * DE];   // [j][e]  = [32][128]
    __shared__ __align__(16) float sR[DH * 128];  // transposed: [j][m_local]

    int n = blockIdx.y;
    int m_base = blockIdx.x * 128;
    int tid = threadIdx.x;

    // fill sT: T[n] (16 KB), fully coalesced
    {
        const float4* gT4 = (const float4*)(g_T + n * (DH * DE));
        float4* sT4 = (float4*)sT;
        #pragma unroll
        for (int k = 0; k < 4; k++) sT4[tid + k * 256] = gT4[tid + k * 256];
    }
    // fill sR transposed: sR[j][ml] = right[m_base+ml][j]
    {
        int ml = tid & 127;
        int jq0 = tid >> 7;
        #pragma unroll
        for (int it = 0; it < 4; it++) {
            int jq = jq0 + it * 2;
            float4 r4 = *(const float4*)(g_right + (m_base + ml) * DH + jq * 4);
            sR[(jq * 4 + 0) * 128 + ml] = r4.x;
            sR[(jq * 4 + 1) * 128 + ml] = r4.y;
            sR[(jq * 4 + 2) * 128 + ml] = r4.z;
            sR[(jq * 4 + 3) * 128 + ml] = r4.w;
        }
    }

    int lane = tid & 31;
    int w    = tid >> 5;
    int e0 = lane * 4;        // this thread's 4 e columns
    int mt = w * 16;          // this warp's 16 m rows (within tile)

    // init accumulators from edge + b_out (loads overlap smem fill latency)
    float4 b4 = *(const float4*)(b_out + e0);
    unsigned long long acc[8][4];
    const float* erow = edge + ((size_t)n * NN + m_base + mt) * DE + e0;
    #pragma unroll
    for (int mp = 0; mp < 8; mp++) {
        float4 ea = *(const float4*)(erow + (2 * mp) * DE);
        float4 eb = *(const float4*)(erow + (2 * mp + 1) * DE);
        acc[mp][0] = pk2(ea.x + b4.x, eb.x + b4.x);
        acc[mp][1] = pk2(ea.y + b4.y, eb.y + b4.y);
        acc[mp][2] = pk2(ea.z + b4.z, eb.z + b4.z);
        acc[mp][3] = pk2(ea.w + b4.w, eb.w + b4.w);
    }
    __syncthreads();

    // mainloop over j: 32 FFMA2 per thread per j (FMA-pipe bound)
    #pragma unroll 8
    for (int j = 0; j < DH; j++) {
        float4 t4 = *(const float4*)(sT + j * DE + e0);
        unsigned long long t0 = pk2(t4.x, t4.x);
        unsigned long long t1 = pk2(t4.y, t4.y);
        unsigned long long t2 = pk2(t4.z, t4.z);
        unsigned long long t3 = pk2(t4.w, t4.w);
        const float* rj = sR + j * 128 + mt;
        #pragma unroll
        for (int mp = 0; mp < 8; mp++) {
            unsigned long long r2 = *(const unsigned long long*)(rj + 2 * mp);
            fma2(acc[mp][0], r2, t0);
            fma2(acc[mp][1], r2, t1);
            fma2(acc[mp][2], r2, t2);
            fma2(acc[mp][3], r2, t3);
        }
    }

    // epilogue: pure STG.128 stream
    float* orow = out + ((size_t)n * NN + m_base + mt) * DE + e0;
    #pragma unroll
    for (int mp = 0; mp < 8; mp++) {
        float a0, b0, a1, b1, a2, b2, a3, b3;
        upk2(acc[mp][0], a0, b0);
        upk2(acc[mp][1], a1, b1);
        upk2(acc[mp][2], a2, b2);
        upk2(acc[mp][3], a3, b3);
        *(float4*)(orow + (2 * mp) * DE)     = make_float4(a0, a1, a2, a3);
        *(float4*)(orow + (2 * mp + 1) * DE) = make_float4(b0, b1, b2, b3);
    }
}

// ---------------- launch ----------------
extern "C" void kernel_launch(void* const* d_in, const int* in_sizes, int n_in,
                              void* d_out, int out_size) {
    const float* node   = (const float*)d_in[0];
    const float* edge   = (const float*)d_in[1];
    const float* ln_w   = (const float*)d_in[2];
    const float* ln_b   = (const float*)d_in[3];
    const float* w_left = (const float*)d_in[4];
    const float* b_left = (const float*)d_in[5];
    const float* w_right= (const float*)d_in[6];
    const float* b_right= (const float*)d_in[7];
    const float* w_out  = (const float*)d_in[8];
    const float* b_out  = (const float*)d_in[9];
    float* out = (float*)d_out;

    p1_kernel<<<NN, 256>>>(node, ln_w, ln_b, w_left, b_left, w_right, b_right);
    p2_kernel<<<dim3(32, 16), 256>>>(w_out);
    outk_kernel<<<dim3(4, NN), 256>>>(edge, b_out, out);
}